// round 12
// baseline (speedup 1.0000x reference)
#include <cuda_runtime.h>
#include <cstdint>

// Problem constants: pred_softmax (16, 11, 1, 512, 512) fp32; use parts 0..9.
#define B_DIM   16
#define P_FULL  11
#define P_USE   10
#define HW      512
#define NIMG    160
#define SLABS_PER_IMG 16                 // 32 rows per slab
#define NSLAB   2560
#define GRID    592                      // 148 SMs x 4 CTAs
#define THREADS 288                      // 256 consumers + 1 producer warp
#define NSTAGE  4
#define STAGE_FLOATS 2048                // 4 rows x 512 cols = 8 KB
#define STAGE_BYTES  8192
#define STAGES_PER_SLAB 8                // 8 x 4 rows = 32-row slab

// Per-slab partials [S,Sx,Sxx,Sy,Syy]; per-image contributions; tickets.
__device__ __align__(16) float g_part[5][NSLAB];
__device__ __align__(16) float g_img[NIMG];
__device__ unsigned int g_work;            // NSLAB increments/launch, wraps->0
__device__ unsigned int g_imgtick[NIMG];   // 16 increments each, wrap->0
__device__ unsigned int g_done;            // 160 increments, wrap->0

__device__ __forceinline__ uint32_t smem_u32(const void* p) {
    uint32_t a;
    asm("{ .reg .u64 t; cvta.to.shared.u64 t, %1; cvt.u32.u64 %0, t; }"
        : "=r"(a) : "l"(p));
    return a;
}
#define MB_INIT(a, c) \
    asm volatile("mbarrier.init.shared.b64 [%0], %1;" :: "r"(a), "r"(c) : "memory")
#define MB_ARRIVE(a) \
    asm volatile("mbarrier.arrive.shared.b64 _, [%0];" :: "r"(a) : "memory")
#define MB_ARRIVE_TX(a, bytes) \
    asm volatile("mbarrier.arrive.expect_tx.shared.b64 _, [%0], %1;" \
                 :: "r"(a), "r"(bytes) : "memory")
#define CP_BULK(dst, src, bytes, mbar) \
    asm volatile("cp.async.bulk.shared::cluster.global.mbarrier::complete_tx::bytes " \
                 "[%0], [%1], %2, [%3];" \
                 :: "r"(dst), "l"(src), "r"(bytes), "r"(mbar) : "memory")

__device__ __forceinline__ void mb_wait(uint32_t mbar, uint32_t parity) {
    uint32_t done;
    asm volatile(
        "{\n\t.reg .pred p;\n\t"
        "mbarrier.try_wait.parity.acquire.cta.shared::cta.b64 p, [%1], %2;\n\t"
        "selp.b32 %0, 1, 0, p;\n\t}"
        : "=r"(done) : "r"(mbar), "r"(parity) : "memory");
    while (!done) {
        asm volatile(
            "{\n\t.reg .pred p;\n\t"
            "mbarrier.try_wait.parity.acquire.cta.shared::cta.b64 p, [%1], %2, 0x989680;\n\t"
            "selp.b32 %0, 1, 0, p;\n\t}"
            : "=r"(done) : "r"(mbar), "r"(parity) : "memory");
    }
}

__global__ __launch_bounds__(THREADS, 4) void fused_kernel(const float* __restrict__ in,
                                                           float* __restrict__ out) {
    __shared__ __align__(128) float s_buf[NSTAGE][STAGE_FLOATS];   // 32 KB ring
    __shared__ __align__(8) unsigned long long s_mb[2 * NSTAGE];   // full[0..3], empty[0..3]
    __shared__ int   s_meta[NSTAGE];
    __shared__ float sh[2][8][5];

    const int tid = threadIdx.x;
    const uint32_t mb_base = smem_u32(&s_mb[0]);
    const uint32_t full_mb  = mb_base;          // + stage*8
    const uint32_t empty_mb = mb_base + NSTAGE * 8;

    if (tid == 0) {
        #pragma unroll
        for (int s = 0; s < NSTAGE; ++s) {
            MB_INIT(full_mb + s * 8, 1);     // producer arrive + tx bytes
            MB_INIT(empty_mb + s * 8, 256);  // all consumers arrive
        }
    }
    __syncthreads();

    if (tid >= 256) {
        // ------------------- Producer (warp 8, lane 0) -------------------
        if (tid == 256) {
            int pstage = 0, pphase = 1;   // phase 1: first empty-waits pass
            int slab = blockIdx.x;        // static first assignment
            while (slab < NSLAB) {
                const int img = slab >> 4;
                const int sub = slab & 15;
                const int b = img / P_USE;
                const int p = img % P_USE;
                const float* gbase = in + ((size_t)b * P_FULL + p) * (size_t)(HW * HW)
                                        + (size_t)sub * (32 * HW);
                #pragma unroll
                for (int s2 = 0; s2 < STAGES_PER_SLAB; ++s2) {
                    mb_wait(empty_mb + pstage * 8, (uint32_t)pphase);
                    s_meta[pstage] = slab * 8 + s2;
                    MB_ARRIVE_TX(full_mb + pstage * 8, STAGE_BYTES);
                    CP_BULK(smem_u32(&s_buf[pstage][0]),
                            gbase + s2 * STAGE_FLOATS, STAGE_BYTES,
                            full_mb + pstage * 8);
                    if (++pstage == NSTAGE) { pstage = 0; pphase ^= 1; }
                }
                slab = GRID + (int)atomicInc(&g_work, NSLAB - 1);
            }
            // Poison: one arrive-only completion with meta = -1.
            mb_wait(empty_mb + pstage * 8, (uint32_t)pphase);
            s_meta[pstage] = -1;
            MB_ARRIVE(full_mb + pstage * 8);
        }
        return;
    }

    // ------------------- Consumers (tids 0..255, warps 0..7) -------------------
    const int wid = tid >> 5, lid = tid & 31;
    const float inv = 2.0f / (float)HW;
    const float x0 = (float)(4 * (tid & 127)) * inv - 1.0f;
    const float x1 = x0 + inv;
    const float x2 = x0 + 2.0f * inv;
    const float x3 = x0 + 3.0f * inv;
    const float x0s = x0 * x0, x1s = x1 * x1, x2s = x2 * x2, x3s = x3 * x3;
    const float roff = (float)(tid >> 7);     // 0 or 1: row within stage-half

    int cstage = 0, cphase = 0;
    int par = 0;                              // sh[] double-buffer parity
    float S = 0.f, Sx = 0.f, Sxx = 0.f, Sy = 0.f, Syy = 0.f;

    for (;;) {
        mb_wait(full_mb + cstage * 8, (uint32_t)cphase);
        const int meta = s_meta[cstage];
        if (meta < 0) break;

        const float4* sb = (const float4*)&s_buf[cstage][0];
        float4 v0 = sb[tid];
        float4 v1 = sb[tid + 256];
        MB_ARRIVE(empty_mb + cstage * 8);     // data now in registers

        const int s2 = meta & 7;
        const int slab = meta >> 3;
        const int sub = slab & 15;
        const float rowb = (float)(sub * 32 + s2 * 4);
        const float ym0 = (rowb + roff) * inv - 1.0f;
        const float ym1 = ym0 + 2.0f * inv;

        float rs0 = (v0.x + v0.y) + (v0.z + v0.w);
        float rs1 = (v1.x + v1.y) + (v1.z + v1.w);
        S += rs0 + rs1;
        Sy = fmaf(rs0, ym0, fmaf(rs1, ym1, Sy));
        Syy = fmaf(rs0 * ym0, ym0, fmaf(rs1 * ym1, ym1, Syy));
        Sx  = fmaf(v0.x, x0,  fmaf(v0.y, x1,  fmaf(v0.z, x2,  fmaf(v0.w, x3,  Sx))));
        Sx  = fmaf(v1.x, x0,  fmaf(v1.y, x1,  fmaf(v1.z, x2,  fmaf(v1.w, x3,  Sx))));
        Sxx = fmaf(v0.x, x0s, fmaf(v0.y, x1s, fmaf(v0.z, x2s, fmaf(v0.w, x3s, Sxx))));
        Sxx = fmaf(v1.x, x0s, fmaf(v1.y, x1s, fmaf(v1.z, x2s, fmaf(v1.w, x3s, Sxx))));

        if (s2 == STAGES_PER_SLAB - 1) {
            // -------- Slab epilogue: reduce 5 sums over 256 consumer threads --------
            #pragma unroll
            for (int off = 16; off > 0; off >>= 1) {
                S   += __shfl_xor_sync(0xFFFFFFFFu, S,   off);
                Sx  += __shfl_xor_sync(0xFFFFFFFFu, Sx,  off);
                Sxx += __shfl_xor_sync(0xFFFFFFFFu, Sxx, off);
                Sy  += __shfl_xor_sync(0xFFFFFFFFu, Sy,  off);
                Syy += __shfl_xor_sync(0xFFFFFFFFu, Syy, off);
            }
            if (lid == 0) {
                sh[par][wid][0] = S;  sh[par][wid][1] = Sx; sh[par][wid][2] = Sxx;
                sh[par][wid][3] = Sy; sh[par][wid][4] = Syy;
            }
            asm volatile("bar.sync 1, 256;" ::: "memory");
            if (tid == 0) {
                #pragma unroll
                for (int c = 0; c < 5; ++c) {
                    float acc = 0.f;
                    #pragma unroll
                    for (int w = 0; w < 8; ++w) acc += sh[par][w][c];
                    g_part[c][slab] = acc;
                }
                __threadfence();
                const int img = slab >> 4;
                unsigned int it = atomicInc(&g_imgtick[img], SLABS_PER_IMG - 1);
                if (it == SLABS_PER_IMG - 1) {
                    // Image complete: reduce its 16 slab-partials (deterministic order).
                    __threadfence();
                    float s[5];
                    #pragma unroll
                    for (int c = 0; c < 5; ++c) {
                        const float4* p4 = (const float4*)&g_part[c][img * SLABS_PER_IMG];
                        float4 a = __ldcg(&p4[0]), bq = __ldcg(&p4[1]);
                        float4 cc = __ldcg(&p4[2]), d = __ldcg(&p4[3]);
                        s[c] = ((a.x + a.y) + (a.z + a.w)) + ((bq.x + bq.y) + (bq.z + bq.w))
                             + ((cc.x + cc.y) + (cc.z + cc.w)) + ((d.x + d.y) + (d.z + d.w));
                    }
                    float k    = s[0] + 1e-8f;
                    float invk = 1.0f / k;
                    float xc   = s[1] * invk;
                    float yc   = s[3] * invk;
                    float spdf = s[0] * invk;
                    float vx = s[2] * invk - 2.0f * xc * xc + xc * xc * spdf;
                    float vy = s[4] * invk - 2.0f * yc * yc + yc * yc * spdf;
                    g_img[img] = vx + vy;
                    __threadfence();
                    unsigned int d2 = atomicInc(&g_done, NIMG - 1);
                    if (d2 == NIMG - 1) {
                        // All images done: fixed-order final sum.
                        __threadfence();
                        float acc = 0.f;
                        #pragma unroll
                        for (int i = 0; i < NIMG / 4; ++i) {
                            float4 t = __ldcg((const float4*)&g_img[4 * i]);
                            acc += (t.x + t.y) + (t.z + t.w);
                        }
                        out[0] = acc / (float)B_DIM;
                    }
                }
            }
            S = Sx = Sxx = Sy = Syy = 0.f;
            par ^= 1;
        }
        if (++cstage == NSTAGE) { cstage = 0; cphase ^= 1; }
    }
}

extern "C" void kernel_launch(void* const* d_in, const int* in_sizes, int n_in,
                              void* d_out, int out_size) {
    const float* in = (const float*)d_in[0];
    float* out = (float*)d_out;
    fused_kernel<<<GRID, THREADS>>>(in, out);
}

// round 14
// speedup vs baseline: 1.0196x; 1.0196x over previous
#include <cuda_runtime.h>
#include <cstdint>

// Problem constants: pred_softmax (16, 11, 1, 512, 512) fp32; use parts 0..9.
#define B_DIM   16
#define P_FULL  11
#define P_USE   10
#define HW      512
#define NIMG    160
#define SLABS_PER_IMG 16                 // 32 rows per slab
#define NSLAB   2560
#define GRID    888                      // 148 SMs x 6 CTAs: one wave
#define NCONS   128                      // 4 consumer warps
#define THREADS 160                      // +1 producer warp
#define NSTAGE  2
#define STAGE_FLOATS 4096                // 8 rows x 512 cols = 16 KB
#define STAGE_BYTES  16384
#define STAGES_PER_SLAB 4                // 4 x 8 rows = 32-row slab

// Per-slab partials [S,Sx,Sxx,Sy,Syy]; per-image contributions; tickets.
__device__ __align__(16) float g_part[5][NSLAB];
__device__ __align__(16) float g_img[NIMG];
__device__ unsigned int g_work;            // NSLAB increments/launch, wraps->0
__device__ unsigned int g_imgtick[NIMG];   // 16 increments each, wrap->0
__device__ unsigned int g_done;            // 160 increments, wrap->0

__device__ __forceinline__ uint32_t smem_u32(const void* p) {
    uint32_t a;
    asm("{ .reg .u64 t; cvta.to.shared.u64 t, %1; cvt.u32.u64 %0, t; }"
        : "=r"(a) : "l"(p));
    return a;
}
#define MB_INIT(a, c) \
    asm volatile("mbarrier.init.shared.b64 [%0], %1;" :: "r"(a), "r"(c) : "memory")
#define MB_ARRIVE(a) \
    asm volatile("mbarrier.arrive.shared.b64 _, [%0];" :: "r"(a) : "memory")
#define MB_ARRIVE_TX(a, bytes) \
    asm volatile("mbarrier.arrive.expect_tx.shared.b64 _, [%0], %1;" \
                 :: "r"(a), "r"(bytes) : "memory")
#define CP_BULK(dst, src, bytes, mbar) \
    asm volatile("cp.async.bulk.shared::cluster.global.mbarrier::complete_tx::bytes " \
                 "[%0], [%1], %2, [%3];" \
                 :: "r"(dst), "l"(src), "r"(bytes), "r"(mbar) : "memory")

__device__ __forceinline__ void mb_wait(uint32_t mbar, uint32_t parity) {
    uint32_t done;
    asm volatile(
        "{\n\t.reg .pred p;\n\t"
        "mbarrier.try_wait.parity.acquire.cta.shared::cta.b64 p, [%1], %2;\n\t"
        "selp.b32 %0, 1, 0, p;\n\t}"
        : "=r"(done) : "r"(mbar), "r"(parity) : "memory");
    while (!done) {
        asm volatile(
            "{\n\t.reg .pred p;\n\t"
            "mbarrier.try_wait.parity.acquire.cta.shared::cta.b64 p, [%1], %2, 0x989680;\n\t"
            "selp.b32 %0, 1, 0, p;\n\t}"
            : "=r"(done) : "r"(mbar), "r"(parity) : "memory");
    }
}

__global__ __launch_bounds__(THREADS, 6) void fused_kernel(const float* __restrict__ in,
                                                           float* __restrict__ out) {
    __shared__ __align__(128) float s_buf[NSTAGE][STAGE_FLOATS];   // 32 KB ring
    __shared__ __align__(8) unsigned long long s_mb[2 * NSTAGE];   // full[], empty[]
    __shared__ int   s_meta[NSTAGE];
    __shared__ float sh[2][4][5];

    const int tid = threadIdx.x;
    const uint32_t mb_base = smem_u32(&s_mb[0]);
    const uint32_t full_mb  = mb_base;          // + stage*8
    const uint32_t empty_mb = mb_base + NSTAGE * 8;

    if (tid == 0) {
        #pragma unroll
        for (int s = 0; s < NSTAGE; ++s) {
            MB_INIT(full_mb + s * 8, 1);   // producer arrive + tx bytes
            MB_INIT(empty_mb + s * 8, 4);  // one elected arrive per consumer warp
        }
    }
    __syncthreads();

    if (tid >= NCONS) {
        // ------------------- Producer (warp 4, lane 0) -------------------
        if (tid == NCONS) {
            int pstage = 0, pphase = 1;   // phase 1: first empty-waits pass
            int slab = blockIdx.x;        // static first assignment
            while (slab < NSLAB) {
                const int img = slab >> 4;
                const int sub = slab & 15;
                const int b = img / P_USE;
                const int p = img % P_USE;
                const float* gbase = in + ((size_t)b * P_FULL + p) * (size_t)(HW * HW)
                                        + (size_t)sub * (32 * HW);
                #pragma unroll
                for (int s2 = 0; s2 < STAGES_PER_SLAB; ++s2) {
                    mb_wait(empty_mb + pstage * 8, (uint32_t)pphase);
                    s_meta[pstage] = slab * 4 + s2;
                    MB_ARRIVE_TX(full_mb + pstage * 8, STAGE_BYTES);
                    CP_BULK(smem_u32(&s_buf[pstage][0]),
                            gbase + s2 * STAGE_FLOATS, STAGE_BYTES,
                            full_mb + pstage * 8);
                    if (++pstage == NSTAGE) { pstage = 0; pphase ^= 1; }
                }
                slab = GRID + (int)atomicInc(&g_work, NSLAB - 1);
            }
            // Poison: one arrive-only completion with meta = -1.
            mb_wait(empty_mb + pstage * 8, (uint32_t)pphase);
            s_meta[pstage] = -1;
            MB_ARRIVE(full_mb + pstage * 8);
        }
        return;
    }

    // --------------- Consumers (tids 0..127, warps 0..3) ---------------
    const int wid = tid >> 5, lid = tid & 31;
    const float inv = 2.0f / (float)HW;     // exact in fp32
    // Thread t owns column-quad t for the whole kernel.
    const float x0 = (float)(4 * tid) * inv - 1.0f;
    const float x1 = x0 + inv;
    const float x2 = x0 + 2.0f * inv;
    const float x3 = x0 + 3.0f * inv;
    const float x0s = x0 * x0, x1s = x1 * x1, x2s = x2 * x2, x3s = x3 * x3;

    int cstage = 0, cphase = 0;
    int par = 0;                            // sh[] double-buffer parity
    float S = 0.f, Sx = 0.f, Sxx = 0.f, Sy = 0.f, Syy = 0.f;

    for (;;) {
        mb_wait(full_mb + cstage * 8, (uint32_t)cphase);
        const int meta = s_meta[cstage];
        if (meta < 0) break;

        // Batch all 8 row-loads (LDS.128, conflict-free: stride 2KB).
        const float4* sb = (const float4*)&s_buf[cstage][0];
        float4 v[8];
        #pragma unroll
        for (int j = 0; j < 8; ++j) v[j] = sb[tid + 128 * j];
        __syncwarp();
        if (lid == 0) MB_ARRIVE(empty_mb + cstage * 8);   // per-warp release

        const int s2   = meta & 3;
        const int slab = meta >> 2;
        const int sub  = slab & 15;
        const float ym0 = (float)(sub * 32 + s2 * 8) * inv - 1.0f;

        // Moment-shift over the 8 rows (fi = j is a compile-time constant).
        float t0 = 0.f, t1 = 0.f, t2 = 0.f;
        #pragma unroll
        for (int j = 0; j < 8; ++j) {
            const float fj = (float)j;
            float rs = (v[j].x + v[j].y) + (v[j].z + v[j].w);
            t0 += rs;
            t1 = fmaf(rs, fj, t1);
            t2 = fmaf(rs, fj * fj, t2);
            Sx  = fmaf(v[j].x, x0,  fmaf(v[j].y, x1,  fmaf(v[j].z, x2,  fmaf(v[j].w, x3,  Sx))));
            Sxx = fmaf(v[j].x, x0s, fmaf(v[j].y, x1s, fmaf(v[j].z, x2s, fmaf(v[j].w, x3s, Sxx))));
        }
        S  += t0;
        Sy  = fmaf(ym0, t0, fmaf(inv, t1, Sy));
        Syy = fmaf(ym0 * ym0, t0, fmaf(2.0f * ym0 * inv, t1, fmaf(inv * inv, t2, Syy)));

        if (s2 == STAGES_PER_SLAB - 1) {
            // ---- Slab epilogue: reduce 5 sums over 128 consumer threads ----
            #pragma unroll
            for (int off = 16; off > 0; off >>= 1) {
                S   += __shfl_xor_sync(0xFFFFFFFFu, S,   off);
                Sx  += __shfl_xor_sync(0xFFFFFFFFu, Sx,  off);
                Sxx += __shfl_xor_sync(0xFFFFFFFFu, Sxx, off);
                Sy  += __shfl_xor_sync(0xFFFFFFFFu, Sy,  off);
                Syy += __shfl_xor_sync(0xFFFFFFFFu, Syy, off);
            }
            if (lid == 0) {
                sh[par][wid][0] = S;  sh[par][wid][1] = Sx; sh[par][wid][2] = Sxx;
                sh[par][wid][3] = Sy; sh[par][wid][4] = Syy;
            }
            asm volatile("bar.sync 1, 128;" ::: "memory");
            if (tid == 0) {
                #pragma unroll
                for (int c = 0; c < 5; ++c) {
                    float acc = 0.f;
                    #pragma unroll
                    for (int w = 0; w < 4; ++w) acc += sh[par][w][c];
                    g_part[c][slab] = acc;
                }
                __threadfence();
                const int img = slab >> 4;
                unsigned int it = atomicInc(&g_imgtick[img], SLABS_PER_IMG - 1);
                if (it == SLABS_PER_IMG - 1) {
                    // Image complete: reduce its 16 slab-partials (fixed order).
                    __threadfence();
                    float s[5];
                    #pragma unroll
                    for (int c = 0; c < 5; ++c) {
                        const float4* p4 = (const float4*)&g_part[c][img * SLABS_PER_IMG];
                        float4 a = __ldcg(&p4[0]), bq = __ldcg(&p4[1]);
                        float4 cc = __ldcg(&p4[2]), d = __ldcg(&p4[3]);
                        s[c] = ((a.x + a.y) + (a.z + a.w)) + ((bq.x + bq.y) + (bq.z + bq.w))
                             + ((cc.x + cc.y) + (cc.z + cc.w)) + ((d.x + d.y) + (d.z + d.w));
                    }
                    float k    = s[0] + 1e-8f;
                    float invk = 1.0f / k;
                    float xc   = s[1] * invk;
                    float yc   = s[3] * invk;
                    float spdf = s[0] * invk;
                    float vx = s[2] * invk - 2.0f * xc * xc + xc * xc * spdf;
                    float vy = s[4] * invk - 2.0f * yc * yc + yc * yc * spdf;
                    g_img[img] = vx + vy;
                    __threadfence();
                    unsigned int d2 = atomicInc(&g_done, NIMG - 1);
                    if (d2 == NIMG - 1) {
                        __threadfence();
                        float acc = 0.f;
                        #pragma unroll
                        for (int i = 0; i < NIMG / 4; ++i) {
                            float4 t = __ldcg((const float4*)&g_img[4 * i]);
                            acc += (t.x + t.y) + (t.z + t.w);
                        }
                        out[0] = acc / (float)B_DIM;
                    }
                }
            }
            S = Sx = Sxx = Sy = Syy = 0.f;
            par ^= 1;
        }
        if (++cstage == NSTAGE) { cstage = 0; cphase ^= 1; }
    }
}

extern "C" void kernel_launch(void* const* d_in, const int* in_sizes, int n_in,
                              void* d_out, int out_size) {
    const float* in = (const float*)d_in[0];
    float* out = (float*)d_out;
    fused_kernel<<<GRID, THREADS>>>(in, out);
}